// round 12
// baseline (speedup 1.0000x reference)
#include <cuda_runtime.h>
#include <math.h>
#include <float.h>

#define B_ 8
#define T_ 48
#define N_ 512
#define F_ 16
#define S_ 12
#define H_ 128
#define NH_ 8
#define HZ_ 6
#define NC_ 3
#define BN_ (B_*N_)   /* 4096 */

#define OFF_REG   0L
#define OFF_RISK  24576L
#define OFF_WARN  98304L
#define OFF_TATTN 122880L
#define OFF_ALPHA 9560064L

// ---------------- scratch ----------------
__device__ __align__(16) float g_W2T[16*384];
__device__ __align__(16) float g_b2[384];
__device__ __align__(16) float g_Mh[8*256];
__device__ __align__(16) float g_rh[8*16];
__device__ __align__(16) float g_ch[8*16];
__device__ __align__(16) float g_cst[8];
__device__ __align__(16) float g_hlast[BN_*H_];
__device__ __align__(16) float g_olast[BN_*H_];
__device__ __align__(16) float g_node3[BN_*3*H_];
__device__ __align__(16) float g_gh[BN_*H_];
__device__ __align__(16) float g_s1[BN_];
__device__ __align__(16) float g_s2[BN_];

// ---------------- helpers ----------------
__device__ __forceinline__ float warp_red_sum(float v) {
    #pragma unroll
    for (int o = 16; o > 0; o >>= 1) v += __shfl_xor_sync(0xffffffffu, v, o);
    return v;
}
__device__ __forceinline__ float warp_red_max(float v) {
    #pragma unroll
    for (int o = 16; o > 0; o >>= 1) v = fmaxf(v, __shfl_xor_sync(0xffffffffu, v, o));
    return v;
}

// ---------------- single-block prep: W2T/b2 then Mh/rh/ch/cst ----------------
__global__ __launch_bounds__(384) void prep_kernel(
    const float* __restrict__ in_w, const float* __restrict__ in_b,
    const float* __restrict__ proj_w, const float* __restrict__ proj_b)
{
    __shared__ float spw[128*16];
    __shared__ float spb[128];
    const int tid = threadIdx.x;   // 384

    for (int i = tid; i < 2048; i += 384) spw[i] = proj_w[i];
    if (tid < 128) spb[tid] = proj_b[tid];
    __syncthreads();

    // phase 1: row j = tid of fused weight/bias
    {
        float accf[16];
        #pragma unroll
        for (int f = 0; f < 16; f++) accf[f] = 0.f;
        float accb = 0.f;
        for (int d = 0; d < 128; d++) {
            float w = in_w[tid*128 + d];
            accb = fmaf(w, spb[d], accb);
            #pragma unroll
            for (int f = 0; f < 16; f++) accf[f] = fmaf(w, spw[d*16 + f], accf[f]);
        }
        g_b2[tid] = accb + in_b[tid];
        #pragma unroll
        for (int f = 0; f < 16; f++) g_W2T[f*384 + tid] = accf[f];
    }
    __syncthreads();   // global writes by block visible to block

    // phase 2: Mh (8*16*16 = 2048 entries)
    for (int idx = tid; idx < 2048; idx += 384) {
        int h = idx >> 8, f = (idx >> 4) & 15, g = idx & 15;
        float s = 0.f;
        #pragma unroll
        for (int d = 0; d < 16; d++)
            s = fmaf(g_W2T[f*384 + h*16 + d], g_W2T[g*384 + 128 + h*16 + d], s);
        g_Mh[h*256 + f*16 + g] = 0.25f*s;
    }
    // phase 3: rh/ch/cst (8*33 = 264 entries)
    for (int idx = tid; idx < 264; idx += 384) {
        int h = idx / 33, r = idx - h*33;
        if (r < 16) {
            float s = 0.f;
            #pragma unroll
            for (int d = 0; d < 16; d++)
                s = fmaf(g_W2T[r*384 + h*16 + d], g_b2[128 + h*16 + d], s);
            g_rh[h*16 + r] = 0.25f*s;
        } else if (r < 32) {
            int g = r - 16;
            float s = 0.f;
            #pragma unroll
            for (int d = 0; d < 16; d++)
                s = fmaf(g_b2[h*16 + d], g_W2T[g*384 + 128 + h*16 + d], s);
            g_ch[h*16 + g] = 0.25f*s;
        } else {
            float s = 0.f;
            #pragma unroll
            for (int d = 0; d < 16; d++)
                s = fmaf(g_b2[h*16 + d], g_b2[128 + h*16 + d], s);
            g_cst[h] = 0.25f*s;
        }
    }
}

// ---------------- attention v4 (proven @190us, unchanged) ----------------
#define XS 20
#define YS 16
#define SSL 52
#define AX   0
#define AY   960
#define AS   4032
#define AU   14016
#define AW   14208
#define AXB  14400
#define ATTN4_FLOATS 14464

__global__ __launch_bounds__(256,3) void attn4_kernel(const float* __restrict__ x,
    const float* __restrict__ proj_w, const float* __restrict__ proj_b,
    const float* __restrict__ x_static, const float* __restrict__ stat_w,
    const float* __restrict__ stat_b,
    float* __restrict__ tattn)
{
    extern __shared__ float sm[];
    const int bn = blockIdx.x;
    const int b = bn >> 9, n = bn & 511;
    const int tid = threadIdx.x;

    if (tid < 192) {
        int t = tid >> 2, q = tid & 3;
        float4 v = ((const float4*)(x + (((long)b*T_ + t)*N_ + n)*F_))[q];
        *(float4*)&sm[AX + t*XS + q*4] = v;
    }
    float racc[12];
    #pragma unroll
    for (int k = 0; k < 12; k++) racc[k] = 0.f;
    __syncthreads();

    const int s = tid >> 6, t64 = tid & 63;
    float* sYs = sm + AY + s*768;
    float* sSs = sm + AS + s*2496;

    for (int g = 0; g < 2; g++) {
        const int h = g*4 + s;
        {
            int i0 = (t64 & 15)*3, q4 = t64 >> 4;
            const float4* M4 = (const float4*)(g_Mh + h*256) + q4;
            float acc[3][4] = {};
            #pragma unroll
            for (int f4 = 0; f4 < 4; f4++) {
                float xr[3][4];
                #pragma unroll
                for (int r = 0; r < 3; r++)
                    *(float4*)xr[r] = *(const float4*)&sm[AX + (i0+r)*XS + f4*4];
                #pragma unroll
                for (int u = 0; u < 4; u++) {
                    float4 mv = M4[(f4*4+u)*4];
                    #pragma unroll
                    for (int r = 0; r < 3; r++) {
                        acc[r][0] = fmaf(xr[r][u], mv.x, acc[r][0]);
                        acc[r][1] = fmaf(xr[r][u], mv.y, acc[r][1]);
                        acc[r][2] = fmaf(xr[r][u], mv.z, acc[r][2]);
                        acc[r][3] = fmaf(xr[r][u], mv.w, acc[r][3]);
                    }
                }
            }
            #pragma unroll
            for (int r = 0; r < 3; r++)
                *(float4*)&sYs[(i0+r)*YS + q4*4] =
                    make_float4(acc[r][0], acc[r][1], acc[r][2], acc[r][3]);
            if (t64 < 48) {
                int i = t64;
                float uu = 0.f, ww = g_cst[h];
                const float4* rh4 = (const float4*)(g_rh + h*16);
                const float4* ch4 = (const float4*)(g_ch + h*16);
                #pragma unroll
                for (int q = 0; q < 4; q++) {
                    float xv[4];
                    *(float4*)xv = *(const float4*)&sm[AX + i*XS + q*4];
                    float4 rv = rh4[q], cv = ch4[q];
                    uu = fmaf(rv.x, xv[0], uu); uu = fmaf(rv.y, xv[1], uu);
                    uu = fmaf(rv.z, xv[2], uu); uu = fmaf(rv.w, xv[3], uu);
                    ww = fmaf(cv.x, xv[0], ww); ww = fmaf(cv.y, xv[1], ww);
                    ww = fmaf(cv.z, xv[2], ww); ww = fmaf(cv.w, xv[3], ww);
                }
                sm[AU + s*48 + i] = uu;
                sm[AW + s*48 + i] = ww;
            }
        }
        __syncthreads();
        {
            int ti = t64 >> 3, tj = t64 & 7;
            int i0 = ti*6, j0 = tj*6;
            float acc[6][6] = {};
            #pragma unroll
            for (int k4 = 0; k4 < 4; k4++) {
                float yv[6][4];
                #pragma unroll
                for (int r = 0; r < 6; r++)
                    *(float4*)yv[r] = *(const float4*)&sYs[(i0+r)*YS + k4*4];
                #pragma unroll
                for (int c = 0; c < 6; c++) {
                    float xc[4];
                    *(float4*)xc = *(const float4*)&sm[AX + (j0+c)*XS + k4*4];
                    #pragma unroll
                    for (int r = 0; r < 6; r++) {
                        acc[r][c] = fmaf(yv[r][0], xc[0], acc[r][c]);
                        acc[r][c] = fmaf(yv[r][1], xc[1], acc[r][c]);
                        acc[r][c] = fmaf(yv[r][2], xc[2], acc[r][c]);
                        acc[r][c] = fmaf(yv[r][3], xc[3], acc[r][c]);
                    }
                }
            }
            float wv[6];
            #pragma unroll
            for (int c = 0; c < 6; c++) wv[c] = sm[AW + s*48 + j0 + c];
            #pragma unroll
            for (int r = 0; r < 6; r++) {
                float uu = sm[AU + s*48 + i0 + r];
                #pragma unroll
                for (int c = 0; c < 6; c++) acc[r][c] += uu + wv[c];
            }
            #pragma unroll
            for (int r = 0; r < 6; r++) {
                float m = acc[r][0];
                #pragma unroll
                for (int c = 1; c < 6; c++) m = fmaxf(m, acc[r][c]);
                m = fmaxf(m, __shfl_xor_sync(0xffffffffu, m, 1));
                m = fmaxf(m, __shfl_xor_sync(0xffffffffu, m, 2));
                m = fmaxf(m, __shfl_xor_sync(0xffffffffu, m, 4));
                float rs = 0.f;
                #pragma unroll
                for (int c = 0; c < 6; c++) {
                    float e = __expf(acc[r][c] - m);
                    acc[r][c] = e;
                    rs += e;
                }
                rs += __shfl_xor_sync(0xffffffffu, rs, 1);
                rs += __shfl_xor_sync(0xffffffffu, rs, 2);
                rs += __shfl_xor_sync(0xffffffffu, rs, 4);
                float inv = 1.f/rs;
                #pragma unroll
                for (int c = 0; c < 6; c++)
                    sSs[(i0+r)*SSL + j0 + c] = acc[r][c]*inv;
            }
        }
        __syncthreads();
        if (tid < 192) {
            #pragma unroll
            for (int q = 0; q < 3; q++) {
                int v = tid + q*192;
                int row = v / 12, c4 = v - row*12;
                int off = AS + row*SSL + c4*4;
                float4 a0 = *(const float4*)&sm[off];
                float4 a1 = *(const float4*)&sm[off + 2496];
                float4 a2 = *(const float4*)&sm[off + 2*2496];
                float4 a3 = *(const float4*)&sm[off + 3*2496];
                racc[q*4+0] += a0.x + a1.x + a2.x + a3.x;
                racc[q*4+1] += a0.y + a1.y + a2.y + a3.y;
                racc[q*4+2] += a0.z + a1.z + a2.z + a3.z;
                racc[q*4+3] += a0.w + a1.w + a2.w + a3.w;
            }
        }
        if (t64 < 16) {
            int f = t64;
            float xb = 0.f;
            #pragma unroll
            for (int k = 0; k < 48; k++)
                xb = fmaf(sSs[47*SSL + k], sm[AX + k*XS + f], xb);
            sm[AXB + s*16 + f] = xb;
        }
        __syncthreads();
        if (t64 < 16) {
            int d = t64;
            int row = 256 + h*16 + d;
            float o = g_b2[row];
            #pragma unroll
            for (int f = 0; f < 16; f++)
                o = fmaf(g_W2T[f*384 + row], sm[AXB + s*16 + f], o);
            g_olast[(long)bn*H_ + h*16 + d] = o;
        }
    }
    if (tid < 192) {
        #pragma unroll
        for (int q = 0; q < 3; q++) {
            int v = tid + q*192;
            int row = v / 12, c4 = v - row*12;
            *(float4*)&tattn[(long)bn*2304 + row*48 + c4*4] =
                make_float4(racc[q*4+0]*0.125f, racc[q*4+1]*0.125f,
                            racc[q*4+2]*0.125f, racc[q*4+3]*0.125f);
        }
    }
    if (tid < 128) {
        float hsum = proj_b[tid];
        const float4* pw = (const float4*)(proj_w + tid*16);
        #pragma unroll
        for (int q = 0; q < 4; q++) {
            float4 w4 = pw[q];
            hsum = fmaf(w4.x, sm[AX + 47*XS + q*4 + 0], hsum);
            hsum = fmaf(w4.y, sm[AX + 47*XS + q*4 + 1], hsum);
            hsum = fmaf(w4.z, sm[AX + 47*XS + q*4 + 2], hsum);
            hsum = fmaf(w4.w, sm[AX + 47*XS + q*4 + 3], hsum);
        }
        g_hlast[(long)bn*H_ + tid] = hsum;
    }
    if (bn < 512 && tid < 128) {
        float v = stat_b[tid];
        #pragma unroll
        for (int f = 0; f < S_; f++)
            v = fmaf(x_static[n*S_ + f], stat_w[tid*S_ + f], v);
        v = fmaxf(v, 0.f);
        #pragma unroll
        for (int bb = 0; bb < B_; bb++)
            g_node3[((long)(bb*N_ + n))*384 + 128 + tid] = v;
    }
}

// ---------------- tail1 (unchanged from proven R11) ----------------
__global__ __launch_bounds__(256) void tail1_kernel(
    const float* __restrict__ out_w, const float* __restrict__ out_b,
    const float* __restrict__ ln1_g, const float* __restrict__ ln1_b,
    const float* __restrict__ ffn_w1, const float* __restrict__ ffn_b1,
    const float* __restrict__ ffn_w2, const float* __restrict__ ffn_b2,
    const float* __restrict__ ln2_g, const float* __restrict__ ln2_b,
    const float* __restrict__ gat_w, const float* __restrict__ gat_a)
{
    const int rowbase = blockIdx.x * 16;
    __shared__ float res1[16][132];
    __shared__ float actB[16][260];
    __shared__ float Bs[32][132];
    const int tid = threadIdx.x;
    const int tx = tid & 31, ty = tid >> 5;

    for (int idx = tid; idx < 16*32; idx += 256) {
        int r = idx >> 5, c4 = idx & 31;
        *(float4*)&actB[r][c4*4] = *(const float4*)&g_olast[(long)(rowbase+r)*128 + c4*4];
    }

    {
        float acc[2][4] = {};
        for (int k0 = 0; k0 < 128; k0 += 32) {
            #pragma unroll
            for (int it = 0; it < 4; it++) {
                int q = tid + it*256;
                int c = q & 127, kq = q >> 7;
                float4 bv = *(const float4*)&out_w[(long)c*128 + k0 + kq*4];
                Bs[kq*4+0][c] = bv.x; Bs[kq*4+1][c] = bv.y;
                Bs[kq*4+2][c] = bv.z; Bs[kq*4+3][c] = bv.w;
            }
            __syncthreads();
            #pragma unroll
            for (int kk = 0; kk < 32; kk++) {
                float a0 = actB[ty][k0+kk], a1 = actB[ty+8][k0+kk];
                float4 b4 = *(const float4*)&Bs[kk][tx*4];
                acc[0][0] = fmaf(a0, b4.x, acc[0][0]); acc[0][1] = fmaf(a0, b4.y, acc[0][1]);
                acc[0][2] = fmaf(a0, b4.z, acc[0][2]); acc[0][3] = fmaf(a0, b4.w, acc[0][3]);
                acc[1][0] = fmaf(a1, b4.x, acc[1][0]); acc[1][1] = fmaf(a1, b4.y, acc[1][1]);
                acc[1][2] = fmaf(a1, b4.z, acc[1][2]); acc[1][3] = fmaf(a1, b4.w, acc[1][3]);
            }
            __syncthreads();
        }
        float4 ob = *(const float4*)&out_b[tx*4];
        float4 g4 = *(const float4*)&ln1_g[tx*4];
        float4 w4 = *(const float4*)&ln1_b[tx*4];
        #pragma unroll
        for (int i = 0; i < 2; i++) {
            int lr = ty + 8*i;
            float4 r4 = *(const float4*)&g_hlast[(long)(rowbase+lr)*128 + tx*4];
            float v[4];
            v[0] = acc[i][0] + ob.x + r4.x; v[1] = acc[i][1] + ob.y + r4.y;
            v[2] = acc[i][2] + ob.z + r4.z; v[3] = acc[i][3] + ob.w + r4.w;
            float m = warp_red_sum(v[0]+v[1]+v[2]+v[3]) * (1.f/128.f);
            float d2 = 0.f;
            #pragma unroll
            for (int j = 0; j < 4; j++) { float d = v[j]-m; d2 += d*d; }
            float var = warp_red_sum(d2) * (1.f/128.f);
            float inv = rsqrtf(var + 1e-5f);
            float4 o;
            o.x = (v[0]-m)*inv*g4.x + w4.x; o.y = (v[1]-m)*inv*g4.y + w4.y;
            o.z = (v[2]-m)*inv*g4.z + w4.z; o.w = (v[3]-m)*inv*g4.w + w4.w;
            *(float4*)&res1[lr][tx*4] = o;
        }
    }
    __syncthreads();

    for (int cb = 0; cb < 2; cb++) {
        float acc[2][4] = {};
        for (int k0 = 0; k0 < 128; k0 += 32) {
            #pragma unroll
            for (int it = 0; it < 4; it++) {
                int q = tid + it*256;
                int c = q & 127, kq = q >> 7;
                float4 bv = *(const float4*)&ffn_w1[(long)(cb*128 + c)*128 + k0 + kq*4];
                Bs[kq*4+0][c] = bv.x; Bs[kq*4+1][c] = bv.y;
                Bs[kq*4+2][c] = bv.z; Bs[kq*4+3][c] = bv.w;
            }
            __syncthreads();
            #pragma unroll
            for (int kk = 0; kk < 32; kk++) {
                float a0 = res1[ty][k0+kk], a1 = res1[ty+8][k0+kk];
                float4 b4 = *(const float4*)&Bs[kk][tx*4];
                acc[0][0] = fmaf(a0, b4.x, acc[0][0]); acc[0][1] = fmaf(a0, b4.y, acc[0][1]);
                acc[0][2] = fmaf(a0, b4.z, acc[0][2]); acc[0][3] = fmaf(a0, b4.w, acc[0][3]);
                acc[1][0] = fmaf(a1, b4.x, acc[1][0]); acc[1][1] = fmaf(a1, b4.y, acc[1][1]);
                acc[1][2] = fmaf(a1, b4.z, acc[1][2]); acc[1][3] = fmaf(a1, b4.w, acc[1][3]);
            }
            __syncthreads();
        }
        float4 fb = *(const float4*)&ffn_b1[cb*128 + tx*4];
        #pragma unroll
        for (int i = 0; i < 2; i++) {
            float v[4];
            v[0] = acc[i][0] + fb.x; v[1] = acc[i][1] + fb.y;
            v[2] = acc[i][2] + fb.z; v[3] = acc[i][3] + fb.w;
            #pragma unroll
            for (int j = 0; j < 4; j++)
                v[j] = 0.5f*v[j]*(1.f + erff(v[j]*0.70710678118654752f));
            *(float4*)&actB[ty + 8*i][cb*128 + tx*4] = make_float4(v[0], v[1], v[2], v[3]);
        }
        __syncthreads();
    }

    {
        float acc[2][4] = {};
        for (int k0 = 0; k0 < 256; k0 += 32) {
            #pragma unroll
            for (int it = 0; it < 4; it++) {
                int q = tid + it*256;
                int c = q & 127, kq = q >> 7;
                float4 bv = *(const float4*)&ffn_w2[(long)c*256 + k0 + kq*4];
                Bs[kq*4+0][c] = bv.x; Bs[kq*4+1][c] = bv.y;
                Bs[kq*4+2][c] = bv.z; Bs[kq*4+3][c] = bv.w;
            }
            __syncthreads();
            #pragma unroll
            for (int kk = 0; kk < 32; kk++) {
                float a0 = actB[ty][k0+kk], a1 = actB[ty+8][k0+kk];
                float4 b4 = *(const float4*)&Bs[kk][tx*4];
                acc[0][0] = fmaf(a0, b4.x, acc[0][0]); acc[0][1] = fmaf(a0, b4.y, acc[0][1]);
                acc[0][2] = fmaf(a0, b4.z, acc[0][2]); acc[0][3] = fmaf(a0, b4.w, acc[0][3]);
                acc[1][0] = fmaf(a1, b4.x, acc[1][0]); acc[1][1] = fmaf(a1, b4.y, acc[1][1]);
                acc[1][2] = fmaf(a1, b4.z, acc[1][2]); acc[1][3] = fmaf(a1, b4.w, acc[1][3]);
            }
            __syncthreads();
        }
        float4 fb = *(const float4*)&ffn_b2[tx*4];
        float4 g4 = *(const float4*)&ln2_g[tx*4];
        float4 w4 = *(const float4*)&ln2_b[tx*4];
        #pragma unroll
        for (int i = 0; i < 2; i++) {
            int lr = ty + 8*i;
            float4 r4 = *(const float4*)&res1[lr][tx*4];
            float v[4];
            v[0] = acc[i][0] + fb.x + r4.x; v[1] = acc[i][1] + fb.y + r4.y;
            v[2] = acc[i][2] + fb.z + r4.z; v[3] = acc[i][3] + fb.w + r4.w;
            float m = warp_red_sum(v[0]+v[1]+v[2]+v[3]) * (1.f/128.f);
            float d2 = 0.f;
            #pragma unroll
            for (int j = 0; j < 4; j++) { float d = v[j]-m; d2 += d*d; }
            float var = warp_red_sum(d2) * (1.f/128.f);
            float inv = rsqrtf(var + 1e-5f);
            float4 o;
            o.x = (v[0]-m)*inv*g4.x + w4.x; o.y = (v[1]-m)*inv*g4.y + w4.y;
            o.z = (v[2]-m)*inv*g4.z + w4.z; o.w = (v[3]-m)*inv*g4.w + w4.w;
            *(float4*)&g_node3[(long)(rowbase+lr)*384 + tx*4] = o;
            *(float4*)&actB[lr][tx*4] = o;
        }
    }
    __syncthreads();
    for (int idx = tid; idx < 16*32; idx += 256) {
        int r = idx >> 5, c4 = idx & 31;
        *(float4*)&actB[r][128 + c4*4] =
            *(const float4*)&g_node3[(long)(rowbase+r)*384 + 128 + c4*4];
    }

    {
        float acc[2][4] = {};
        for (int k0 = 0; k0 < 256; k0 += 32) {
            #pragma unroll
            for (int it = 0; it < 4; it++) {
                int q = tid + it*256;
                int c = q & 127, kq = q >> 7;
                float4 bv = *(const float4*)&gat_w[(long)c*256 + k0 + kq*4];
                Bs[kq*4+0][c] = bv.x; Bs[kq*4+1][c] = bv.y;
                Bs[kq*4+2][c] = bv.z; Bs[kq*4+3][c] = bv.w;
            }
            __syncthreads();
            #pragma unroll
            for (int kk = 0; kk < 32; kk++) {
                float a0 = actB[ty][k0+kk], a1 = actB[ty+8][k0+kk];
                float4 b4 = *(const float4*)&Bs[kk][tx*4];
                acc[0][0] = fmaf(a0, b4.x, acc[0][0]); acc[0][1] = fmaf(a0, b4.y, acc[0][1]);
                acc[0][2] = fmaf(a0, b4.z, acc[0][2]); acc[0][3] = fmaf(a0, b4.w, acc[0][3]);
                acc[1][0] = fmaf(a1, b4.x, acc[1][0]); acc[1][1] = fmaf(a1, b4.y, acc[1][1]);
                acc[1][2] = fmaf(a1, b4.z, acc[1][2]); acc[1][3] = fmaf(a1, b4.w, acc[1][3]);
            }
            __syncthreads();
        }
        float4 a1v = *(const float4*)&gat_a[tx*4];
        float4 a2v = *(const float4*)&gat_a[128 + tx*4];
        #pragma unroll
        for (int i = 0; i < 2; i++) {
            int r = rowbase + ty + 8*i;
            float4 o = make_float4(acc[i][0], acc[i][1], acc[i][2], acc[i][3]);
            *(float4*)&g_gh[(long)r*128 + tx*4] = o;
            float p1 = o.x*a1v.x + o.y*a1v.y + o.z*a1v.z + o.w*a1v.w;
            float p2 = o.x*a2v.x + o.y*a2v.y + o.z*a2v.z + o.w*a2v.w;
            p1 = warp_red_sum(p1);
            p2 = warp_red_sum(p2);
            if (tx == 0) { g_s1[r] = p1; g_s2[r] = p2; }
        }
    }
}

// ---------------- tail2+fuse merged: alpha + alpha@gh + fuse + heads ----------------
// dynamic smem 12288 floats (49152 B), aliased per phase
__global__ __launch_bounds__(256) void tail2fuse_kernel(const int* __restrict__ adj,
    const float* __restrict__ fuse_w, const float* __restrict__ fuse_b,
    const float* __restrict__ hwreg, const float* __restrict__ hbreg,
    const float* __restrict__ hwrisk, const float* __restrict__ hbrisk,
    const float* __restrict__ hwwarn, const float* __restrict__ hbwarn,
    float* __restrict__ out_alpha, float* __restrict__ hout)
{
    extern __shared__ float sm2[];
    float (*alpha_sm)[512] = (float(*)[512])sm2;            // 16x512
    float (*Bs2)[128]      = (float(*)[128])(sm2 + 8192);   // 32x128
    const int rowbase = blockIdx.x * 16;
    const int b = rowbase >> 9;
    const int tid = threadIdx.x;
    const int tx = tid & 31, ty = tid >> 5;

    // ---- alpha softmax (one warp per 2 rows) ----
    #pragma unroll
    for (int rr = 0; rr < 2; rr++) {
        int lr = ty*2 + rr;
        int i = (rowbase + lr) & 511;
        float s1v = g_s1[rowbase + lr];
        float e[16];
        float mloc = -FLT_MAX;
        #pragma unroll
        for (int u = 0; u < 16; u++) {
            int j = tx + 32*u;
            float v = s1v + g_s2[b*N_ + j];
            v = (v >= 0.f) ? v : 0.2f*v;
            if (adj[i*N_ + j] == 0) v = -FLT_MAX;
            e[u] = v;
            mloc = fmaxf(mloc, v);
        }
        float m = warp_red_max(mloc);
        float sloc = 0.f;
        #pragma unroll
        for (int u = 0; u < 16; u++) {
            e[u] = (e[u] == -FLT_MAX) ? 0.f : __expf(e[u] - m);
            sloc += e[u];
        }
        float inv = 1.f / warp_red_sum(sloc);
        #pragma unroll
        for (int u = 0; u < 16; u++) {
            float a = e[u]*inv;
            alpha_sm[lr][tx + 32*u] = a;
            out_alpha[(long)(rowbase + lr)*N_ + tx + 32*u] = a;
        }
    }
    __syncthreads();

    // ---- g_repr = alpha @ gh_b (K=512) -> node3[:,256:384] ----
    {
        const float* ghb = g_gh + (long)b*N_*H_;
        float acc[2][4] = {};
        for (int k0 = 0; k0 < 512; k0 += 32) {
            #pragma unroll
            for (int it = 0; it < 4; it++) {
                int q = tid + it*256;
                int c4 = q & 31, kk = q >> 5;
                *(float4*)&Bs2[kk][c4*4] = *(const float4*)&ghb[(long)(k0+kk)*128 + c4*4];
            }
            __syncthreads();
            #pragma unroll
            for (int kk = 0; kk < 32; kk++) {
                float a0 = alpha_sm[ty][k0+kk], a1 = alpha_sm[ty+8][k0+kk];
                float4 b4 = *(const float4*)&Bs2[kk][tx*4];
                acc[0][0] = fmaf(a0, b4.x, acc[0][0]); acc[0][1] = fmaf(a0, b4.y, acc[0][1]);
                acc[0][2] = fmaf(a0, b4.z, acc[0][2]); acc[0][3] = fmaf(a0, b4.w, acc[0][3]);
                acc[1][0] = fmaf(a1, b4.x, acc[1][0]); acc[1][1] = fmaf(a1, b4.y, acc[1][1]);
                acc[1][2] = fmaf(a1, b4.z, acc[1][2]); acc[1][3] = fmaf(a1, b4.w, acc[1][3]);
            }
            __syncthreads();
        }
        #pragma unroll
        for (int i = 0; i < 2; i++) {
            int r = rowbase + ty + 8*i;
            *(float4*)&g_node3[(long)r*384 + 256 + tx*4] =
                make_float4(acc[i][0], acc[i][1], acc[i][2], acc[i][3]);
        }
    }
    __syncthreads();

    // ---- fuse (K=384, relu) + heads; alias As/Bsf over alpha region ----
    {
        float (*As)[17]   = (float(*)[17])sm2;              // 32x17 = 544
        float (*Bsf)[132] = (float(*)[132])(sm2 + 544);     // 32x132 = 4224
        float acc[2][4] = {};
        for (int k0 = 0; k0 < 384; k0 += 32) {
            #pragma unroll
            for (int it = 0; it < 2; it++) {
                int idx = tid + it*256;
                int r = idx >> 5, kk = idx & 31;
                As[kk][r] = g_node3[(long)(rowbase + r)*384 + k0 + kk];
            }
            #pragma unroll
            for (int it = 0; it < 4; it++) {
                int q = tid + it*256;
                int c = q & 127, kq = q >> 7;
                float4 bv = *(const float4*)&fuse_w[(long)c*384 + k0 + kq*4];
                Bsf[kq*4+0][c] = bv.x; Bsf[kq*4+1][c] = bv.y;
                Bsf[kq*4+2][c] = bv.z; Bsf[kq*4+3][c] = bv.w;
            }
            __syncthreads();
            #pragma unroll
            for (int kk = 0; kk < 32; kk++) {
                float a0 = As[kk][ty], a1 = As[kk][ty + 8];
                float4 b4 = *(const float4*)&Bsf[kk][tx*4];
                acc[0][0] = fmaf(a0, b4.x, acc[0][0]); acc[0][1] = fmaf(a0, b4.y, acc[0][1]);
                acc[0][2] = fmaf(a0, b4.z, acc[0][2]); acc[0][3] = fmaf(a0, b4.w, acc[0][3]);
                acc[1][0] = fmaf(a1, b4.x, acc[1][0]); acc[1][1] = fmaf(a1, b4.y, acc[1][1]);
                acc[1][2] = fmaf(a1, b4.z, acc[1][2]); acc[1][3] = fmaf(a1, b4.w, acc[1][3]);
            }
            __syncthreads();
        }
        float4 b4 = *(const float4*)&fuse_b[tx*4];
        #pragma unroll
        for (int i = 0; i < 2; i++) {
            float4 o;
            o.x = fmaxf(acc[i][0] + b4.x, 0.f); o.y = fmaxf(acc[i][1] + b4.y, 0.f);
            o.z = fmaxf(acc[i][2] + b4.z, 0.f); o.w = fmaxf(acc[i][3] + b4.w, 0.f);
            *(float4*)&Bsf[ty + 8*i][tx*4] = o;
        }
        __syncthreads();
        for (int p = tid; p < 480; p += 256) {
            int r = p / 30, o = p - 30*r;
            const float* w; float bb; long off;
            if (o < 6)       { w = hwreg  + o*H_;        bb = hbreg[o];        off = OFF_REG  + (long)(rowbase+r)*6  + o; }
            else if (o < 24) { int k = o-6;  w = hwrisk + k*H_; bb = hbrisk[k]; off = OFF_RISK + (long)(rowbase+r)*18 + k; }
            else             { int k = o-24; w = hwwarn + k*H_; bb = hbwarn[k]; off = OFF_WARN + (long)(rowbase+r)*6  + k; }
            float sacc = bb;
            #pragma unroll 8
            for (int c = 0; c < H_; c++)
                sacc = fmaf(Bsf[r][c], w[c], sacc);
            hout[off] = sacc;
        }
    }
}

// ---------------- launch ----------------
extern "C" void kernel_launch(void* const* d_in, const int* in_sizes, int n_in,
                              void* d_out, int out_size)
{
    const float* x        = (const float*)d_in[0];
    const float* x_static = (const float*)d_in[1];
    const int*   adj      = (const int*)  d_in[2];
    const float* proj_w   = (const float*)d_in[3];
    const float* proj_b   = (const float*)d_in[4];
    const float* in_w     = (const float*)d_in[5];
    const float* in_b     = (const float*)d_in[6];
    const float* out_w    = (const float*)d_in[7];
    const float* out_b    = (const float*)d_in[8];
    const float* ln1_g    = (const float*)d_in[9];
    const float* ln1_b    = (const float*)d_in[10];
    const float* ffn_w1   = (const float*)d_in[11];
    const float* ffn_b1   = (const float*)d_in[12];
    const float* ffn_w2   = (const float*)d_in[13];
    const float* ffn_b2   = (const float*)d_in[14];
    const float* ln2_g    = (const float*)d_in[15];
    const float* ln2_b    = (const float*)d_in[16];
    const float* stat_w   = (const float*)d_in[17];
    const float* stat_b   = (const float*)d_in[18];
    const float* gat_w    = (const float*)d_in[19];
    const float* gat_a    = (const float*)d_in[20];
    const float* fuse_w   = (const float*)d_in[21];
    const float* fuse_b   = (const float*)d_in[22];
    const float* reg_w    = (const float*)d_in[23];
    const float* reg_b    = (const float*)d_in[24];
    const float* risk_w   = (const float*)d_in[25];
    const float* risk_b   = (const float*)d_in[26];
    const float* warn_w   = (const float*)d_in[27];
    const float* warn_b   = (const float*)d_in[28];
    float* out = (float*)d_out;

    const int ATTN4_SMEM = ATTN4_FLOATS * 4;   // 57856 bytes
    const int T2F_SMEM   = 12288 * 4;          // 49152 bytes
    cudaFuncSetAttribute(attn4_kernel, cudaFuncAttributeMaxDynamicSharedMemorySize, ATTN4_SMEM);
    cudaFuncSetAttribute(tail2fuse_kernel, cudaFuncAttributeMaxDynamicSharedMemorySize, T2F_SMEM);

    // 0: prep (single block)
    prep_kernel<<<1, 384>>>(in_w, in_b, proj_w, proj_b);
    // 1: attention (+hlast +srepr)
    attn4_kernel<<<BN_, 256, ATTN4_SMEM>>>(x, proj_w, proj_b, x_static, stat_w, stat_b,
                                           out + OFF_TATTN);
    // 2: transformer tail + GAT projection
    tail1_kernel<<<BN_/16, 256>>>(out_w, out_b, ln1_g, ln1_b,
                                  ffn_w1, ffn_b1, ffn_w2, ffn_b2, ln2_g, ln2_b,
                                  gat_w, gat_a);
    // 3: alpha + g_repr + fuse + heads
    tail2fuse_kernel<<<BN_/16, 256, T2F_SMEM>>>(adj, fuse_w, fuse_b,
                                 reg_w, reg_b, risk_w, risk_b, warn_w, warn_b,
                                 out + OFF_ALPHA, out);

    (void)in_sizes; (void)n_in; (void)out_size;
}

// round 16
// speedup vs baseline: 1.0140x; 1.0140x over previous
#include <cuda_runtime.h>
#include <math.h>
#include <float.h>

#define B_ 8
#define T_ 48
#define N_ 512
#define F_ 16
#define S_ 12
#define H_ 128
#define NH_ 8
#define HZ_ 6
#define NC_ 3
#define BN_ (B_*N_)   /* 4096 */

#define OFF_REG   0L
#define OFF_RISK  24576L
#define OFF_WARN  98304L
#define OFF_TATTN 122880L
#define OFF_ALPHA 9560064L

// ---------------- scratch ----------------
__device__ __align__(16) float g_W2T[16*384];
__device__ __align__(16) float g_b2[384];
__device__ __align__(16) float g_Mh[8*256];
__device__ __align__(16) float g_rh[8*16];
__device__ __align__(16) float g_ch[8*16];
__device__ __align__(16) float g_cst[8];
__device__ __align__(16) float g_hlast[BN_*H_];
__device__ __align__(16) float g_olast[BN_*H_];
__device__ __align__(16) float g_node3[BN_*3*H_];
__device__ __align__(16) float g_gh[BN_*H_];
__device__ __align__(16) float g_s1[BN_];
__device__ __align__(16) float g_s2[BN_];

// ---------------- helpers ----------------
__device__ __forceinline__ float warp_red_sum(float v) {
    #pragma unroll
    for (int o = 16; o > 0; o >>= 1) v += __shfl_xor_sync(0xffffffffu, v, o);
    return v;
}
__device__ __forceinline__ float warp_red_max(float v) {
    #pragma unroll
    for (int o = 16; o > 0; o >>= 1) v = fmaxf(v, __shfl_xor_sync(0xffffffffu, v, o));
    return v;
}

// ---------------- single-block prep (proven R12) ----------------
__global__ __launch_bounds__(384) void prep_kernel(
    const float* __restrict__ in_w, const float* __restrict__ in_b,
    const float* __restrict__ proj_w, const float* __restrict__ proj_b)
{
    __shared__ float spw[128*16];
    __shared__ float spb[128];
    const int tid = threadIdx.x;

    for (int i = tid; i < 2048; i += 384) spw[i] = proj_w[i];
    if (tid < 128) spb[tid] = proj_b[tid];
    __syncthreads();

    {
        float accf[16];
        #pragma unroll
        for (int f = 0; f < 16; f++) accf[f] = 0.f;
        float accb = 0.f;
        for (int d = 0; d < 128; d++) {
            float w = in_w[tid*128 + d];
            accb = fmaf(w, spb[d], accb);
            #pragma unroll
            for (int f = 0; f < 16; f++) accf[f] = fmaf(w, spw[d*16 + f], accf[f]);
        }
        g_b2[tid] = accb + in_b[tid];
        #pragma unroll
        for (int f = 0; f < 16; f++) g_W2T[f*384 + tid] = accf[f];
    }
    __syncthreads();

    for (int idx = tid; idx < 2048; idx += 384) {
        int h = idx >> 8, f = (idx >> 4) & 15, g = idx & 15;
        float s = 0.f;
        #pragma unroll
        for (int d = 0; d < 16; d++)
            s = fmaf(g_W2T[f*384 + h*16 + d], g_W2T[g*384 + 128 + h*16 + d], s);
        g_Mh[h*256 + f*16 + g] = 0.25f*s;
    }
    for (int idx = tid; idx < 264; idx += 384) {
        int h = idx / 33, r = idx - h*33;
        if (r < 16) {
            float s = 0.f;
            #pragma unroll
            for (int d = 0; d < 16; d++)
                s = fmaf(g_W2T[r*384 + h*16 + d], g_b2[128 + h*16 + d], s);
            g_rh[h*16 + r] = 0.25f*s;
        } else if (r < 32) {
            int g = r - 16;
            float s = 0.f;
            #pragma unroll
            for (int d = 0; d < 16; d++)
                s = fmaf(g_b2[h*16 + d], g_W2T[g*384 + 128 + h*16 + d], s);
            g_ch[h*16 + g] = 0.25f*s;
        } else {
            float s = 0.f;
            #pragma unroll
            for (int d = 0; d < 16; d++)
                s = fmaf(g_b2[h*16 + d], g_b2[128 + h*16 + d], s);
            g_cst[h] = 0.25f*s;
        }
    }
}

// ---------------- attention v4 (proven @190us, unchanged) ----------------
#define XS 20
#define YS 16
#define SSL 52
#define AX   0
#define AY   960
#define AS   4032
#define AU   14016
#define AW   14208
#define AXB  14400
#define ATTN4_FLOATS 14464

__global__ __launch_bounds__(256,3) void attn4_kernel(const float* __restrict__ x,
    const float* __restrict__ proj_w, const float* __restrict__ proj_b,
    const float* __restrict__ x_static, const float* __restrict__ stat_w,
    const float* __restrict__ stat_b,
    float* __restrict__ tattn)
{
    extern __shared__ float sm[];
    const int bn = blockIdx.x;
    const int b = bn >> 9, n = bn & 511;
    const int tid = threadIdx.x;

    if (tid < 192) {
        int t = tid >> 2, q = tid & 3;
        float4 v = ((const float4*)(x + (((long)b*T_ + t)*N_ + n)*F_))[q];
        *(float4*)&sm[AX + t*XS + q*4] = v;
    }
    float racc[12];
    #pragma unroll
    for (int k = 0; k < 12; k++) racc[k] = 0.f;
    __syncthreads();

    const int s = tid >> 6, t64 = tid & 63;
    float* sYs = sm + AY + s*768;
    float* sSs = sm + AS + s*2496;

    for (int g = 0; g < 2; g++) {
        const int h = g*4 + s;
        {
            int i0 = (t64 & 15)*3, q4 = t64 >> 4;
            const float4* M4 = (const float4*)(g_Mh + h*256) + q4;
            float acc[3][4] = {};
            #pragma unroll
            for (int f4 = 0; f4 < 4; f4++) {
                float xr[3][4];
                #pragma unroll
                for (int r = 0; r < 3; r++)
                    *(float4*)xr[r] = *(const float4*)&sm[AX + (i0+r)*XS + f4*4];
                #pragma unroll
                for (int u = 0; u < 4; u++) {
                    float4 mv = M4[(f4*4+u)*4];
                    #pragma unroll
                    for (int r = 0; r < 3; r++) {
                        acc[r][0] = fmaf(xr[r][u], mv.x, acc[r][0]);
                        acc[r][1] = fmaf(xr[r][u], mv.y, acc[r][1]);
                        acc[r][2] = fmaf(xr[r][u], mv.z, acc[r][2]);
                        acc[r][3] = fmaf(xr[r][u], mv.w, acc[r][3]);
                    }
                }
            }
            #pragma unroll
            for (int r = 0; r < 3; r++)
                *(float4*)&sYs[(i0+r)*YS + q4*4] =
                    make_float4(acc[r][0], acc[r][1], acc[r][2], acc[r][3]);
            if (t64 < 48) {
                int i = t64;
                float uu = 0.f, ww = g_cst[h];
                const float4* rh4 = (const float4*)(g_rh + h*16);
                const float4* ch4 = (const float4*)(g_ch + h*16);
                #pragma unroll
                for (int q = 0; q < 4; q++) {
                    float xv[4];
                    *(float4*)xv = *(const float4*)&sm[AX + i*XS + q*4];
                    float4 rv = rh4[q], cv = ch4[q];
                    uu = fmaf(rv.x, xv[0], uu); uu = fmaf(rv.y, xv[1], uu);
                    uu = fmaf(rv.z, xv[2], uu); uu = fmaf(rv.w, xv[3], uu);
                    ww = fmaf(cv.x, xv[0], ww); ww = fmaf(cv.y, xv[1], ww);
                    ww = fmaf(cv.z, xv[2], ww); ww = fmaf(cv.w, xv[3], ww);
                }
                sm[AU + s*48 + i] = uu;
                sm[AW + s*48 + i] = ww;
            }
        }
        __syncthreads();
        {
            int ti = t64 >> 3, tj = t64 & 7;
            int i0 = ti*6, j0 = tj*6;
            float acc[6][6] = {};
            #pragma unroll
            for (int k4 = 0; k4 < 4; k4++) {
                float yv[6][4];
                #pragma unroll
                for (int r = 0; r < 6; r++)
                    *(float4*)yv[r] = *(const float4*)&sYs[(i0+r)*YS + k4*4];
                #pragma unroll
                for (int c = 0; c < 6; c++) {
                    float xc[4];
                    *(float4*)xc = *(const float4*)&sm[AX + (j0+c)*XS + k4*4];
                    #pragma unroll
                    for (int r = 0; r < 6; r++) {
                        acc[r][c] = fmaf(yv[r][0], xc[0], acc[r][c]);
                        acc[r][c] = fmaf(yv[r][1], xc[1], acc[r][c]);
                        acc[r][c] = fmaf(yv[r][2], xc[2], acc[r][c]);
                        acc[r][c] = fmaf(yv[r][3], xc[3], acc[r][c]);
                    }
                }
            }
            float wv[6];
            #pragma unroll
            for (int c = 0; c < 6; c++) wv[c] = sm[AW + s*48 + j0 + c];
            #pragma unroll
            for (int r = 0; r < 6; r++) {
                float uu = sm[AU + s*48 + i0 + r];
                #pragma unroll
                for (int c = 0; c < 6; c++) acc[r][c] += uu + wv[c];
            }
            #pragma unroll
            for (int r = 0; r < 6; r++) {
                float m = acc[r][0];
                #pragma unroll
                for (int c = 1; c < 6; c++) m = fmaxf(m, acc[r][c]);
                m = fmaxf(m, __shfl_xor_sync(0xffffffffu, m, 1));
                m = fmaxf(m, __shfl_xor_sync(0xffffffffu, m, 2));
                m = fmaxf(m, __shfl_xor_sync(0xffffffffu, m, 4));
                float rs = 0.f;
                #pragma unroll
                for (int c = 0; c < 6; c++) {
                    float e = __expf(acc[r][c] - m);
                    acc[r][c] = e;
                    rs += e;
                }
                rs += __shfl_xor_sync(0xffffffffu, rs, 1);
                rs += __shfl_xor_sync(0xffffffffu, rs, 2);
                rs += __shfl_xor_sync(0xffffffffu, rs, 4);
                float inv = 1.f/rs;
                #pragma unroll
                for (int c = 0; c < 6; c++)
                    sSs[(i0+r)*SSL + j0 + c] = acc[r][c]*inv;
            }
        }
        __syncthreads();
        if (tid < 192) {
            #pragma unroll
            for (int q = 0; q < 3; q++) {
                int v = tid + q*192;
                int row = v / 12, c4 = v - row*12;
                int off = AS + row*SSL + c4*4;
                float4 a0 = *(const float4*)&sm[off];
                float4 a1 = *(const float4*)&sm[off + 2496];
                float4 a2 = *(const float4*)&sm[off + 2*2496];
                float4 a3 = *(const float4*)&sm[off + 3*2496];
                racc[q*4+0] += a0.x + a1.x + a2.x + a3.x;
                racc[q*4+1] += a0.y + a1.y + a2.y + a3.y;
                racc[q*4+2] += a0.z + a1.z + a2.z + a3.z;
                racc[q*4+3] += a0.w + a1.w + a2.w + a3.w;
            }
        }
        if (t64 < 16) {
            int f = t64;
            float xb = 0.f;
            #pragma unroll
            for (int k = 0; k < 48; k++)
                xb = fmaf(sSs[47*SSL + k], sm[AX + k*XS + f], xb);
            sm[AXB + s*16 + f] = xb;
        }
        __syncthreads();
        if (t64 < 16) {
            int d = t64;
            int row = 256 + h*16 + d;
            float o = g_b2[row];
            #pragma unroll
            for (int f = 0; f < 16; f++)
                o = fmaf(g_W2T[f*384 + row], sm[AXB + s*16 + f], o);
            g_olast[(long)bn*H_ + h*16 + d] = o;
        }
    }
    if (tid < 192) {
        #pragma unroll
        for (int q = 0; q < 3; q++) {
            int v = tid + q*192;
            int row = v / 12, c4 = v - row*12;
            *(float4*)&tattn[(long)bn*2304 + row*48 + c4*4] =
                make_float4(racc[q*4+0]*0.125f, racc[q*4+1]*0.125f,
                            racc[q*4+2]*0.125f, racc[q*4+3]*0.125f);
        }
    }
    if (tid < 128) {
        float hsum = proj_b[tid];
        const float4* pw = (const float4*)(proj_w + tid*16);
        #pragma unroll
        for (int q = 0; q < 4; q++) {
            float4 w4 = pw[q];
            hsum = fmaf(w4.x, sm[AX + 47*XS + q*4 + 0], hsum);
            hsum = fmaf(w4.y, sm[AX + 47*XS + q*4 + 1], hsum);
            hsum = fmaf(w4.z, sm[AX + 47*XS + q*4 + 2], hsum);
            hsum = fmaf(w4.w, sm[AX + 47*XS + q*4 + 3], hsum);
        }
        g_hlast[(long)bn*H_ + tid] = hsum;
    }
    if (bn < 512 && tid < 128) {
        float v = stat_b[tid];
        #pragma unroll
        for (int f = 0; f < S_; f++)
            v = fmaf(x_static[n*S_ + f], stat_w[tid*S_ + f], v);
        v = fmaxf(v, 0.f);
        #pragma unroll
        for (int bb = 0; bb < B_; bb++)
            g_node3[((long)(bb*N_ + n))*384 + 128 + tid] = v;
    }
}

// prefetch helpers (weights row-major, bt layout: [c][K])
#define PREF_BT(W, ldw, kbase) do { \
    _Pragma("unroll") \
    for (int it = 0; it < 4; it++) { \
        int q = tid + it*256; int c = q & 127, kq = q >> 7; \
        pre[it] = *(const float4*)&(W)[(long)c*(ldw) + (kbase) + kq*4]; \
    } } while(0)
#define STORE_BT() do { \
    _Pragma("unroll") \
    for (int it = 0; it < 4; it++) { \
        int q = tid + it*256; int c = q & 127, kq = q >> 7; \
        Bs[kq*4+0][c] = pre[it].x; Bs[kq*4+1][c] = pre[it].y; \
        Bs[kq*4+2][c] = pre[it].z; Bs[kq*4+3][c] = pre[it].w; \
    } } while(0)

// ---------------- tail1 (R11 structure + register-prefetch K-loops) ----------------
__global__ __launch_bounds__(256) void tail1_kernel(
    const float* __restrict__ out_w, const float* __restrict__ out_b,
    const float* __restrict__ ln1_g, const float* __restrict__ ln1_b,
    const float* __restrict__ ffn_w1, const float* __restrict__ ffn_b1,
    const float* __restrict__ ffn_w2, const float* __restrict__ ffn_b2,
    const float* __restrict__ ln2_g, const float* __restrict__ ln2_b,
    const float* __restrict__ gat_w, const float* __restrict__ gat_a)
{
    const int rowbase = blockIdx.x * 16;
    __shared__ float res1[16][132];
    __shared__ float actB[16][260];
    __shared__ float Bs[32][132];
    const int tid = threadIdx.x;
    const int tx = tid & 31, ty = tid >> 5;
    float4 pre[4];

    for (int idx = tid; idx < 16*32; idx += 256) {
        int r = idx >> 5, c4 = idx & 31;
        *(float4*)&actB[r][c4*4] = *(const float4*)&g_olast[(long)(rowbase+r)*128 + c4*4];
    }

    // ---- stage A: out-proj K=128 + LN1 -> res1 ----
    {
        float acc[2][4] = {};
        PREF_BT(out_w, 128, 0);
        for (int k0 = 0; k0 < 128; k0 += 32) {
            STORE_BT();
            __syncthreads();
            if (k0 + 32 < 128) PREF_BT(out_w, 128, k0 + 32);
            #pragma unroll
            for (int kk = 0; kk < 32; kk++) {
                float a0 = actB[ty][k0+kk], a1 = actB[ty+8][k0+kk];
                float4 b4 = *(const float4*)&Bs[kk][tx*4];
                acc[0][0] = fmaf(a0, b4.x, acc[0][0]); acc[0][1] = fmaf(a0, b4.y, acc[0][1]);
                acc[0][2] = fmaf(a0, b4.z, acc[0][2]); acc[0][3] = fmaf(a0, b4.w, acc[0][3]);
                acc[1][0] = fmaf(a1, b4.x, acc[1][0]); acc[1][1] = fmaf(a1, b4.y, acc[1][1]);
                acc[1][2] = fmaf(a1, b4.z, acc[1][2]); acc[1][3] = fmaf(a1, b4.w, acc[1][3]);
            }
            __syncthreads();
        }
        float4 ob = *(const float4*)&out_b[tx*4];
        float4 g4 = *(const float4*)&ln1_g[tx*4];
        float4 w4 = *(const float4*)&ln1_b[tx*4];
        #pragma unroll
        for (int i = 0; i < 2; i++) {
            int lr = ty + 8*i;
            float4 r4 = *(const float4*)&g_hlast[(long)(rowbase+lr)*128 + tx*4];
            float v[4];
            v[0] = acc[i][0] + ob.x + r4.x; v[1] = acc[i][1] + ob.y + r4.y;
            v[2] = acc[i][2] + ob.z + r4.z; v[3] = acc[i][3] + ob.w + r4.w;
            float m = warp_red_sum(v[0]+v[1]+v[2]+v[3]) * (1.f/128.f);
            float d2 = 0.f;
            #pragma unroll
            for (int j = 0; j < 4; j++) { float d = v[j]-m; d2 += d*d; }
            float var = warp_red_sum(d2) * (1.f/128.f);
            float inv = rsqrtf(var + 1e-5f);
            float4 o;
            o.x = (v[0]-m)*inv*g4.x + w4.x; o.y = (v[1]-m)*inv*g4.y + w4.y;
            o.z = (v[2]-m)*inv*g4.z + w4.z; o.w = (v[3]-m)*inv*g4.w + w4.w;
            *(float4*)&res1[lr][tx*4] = o;
        }
    }
    __syncthreads();

    // ---- stage B: FFN1 K=128 x2 col-blocks + gelu ----
    for (int cb = 0; cb < 2; cb++) {
        float acc[2][4] = {};
        const float* w1 = ffn_w1 + (long)cb*128*128;
        PREF_BT(w1, 128, 0);
        for (int k0 = 0; k0 < 128; k0 += 32) {
            STORE_BT();
            __syncthreads();
            if (k0 + 32 < 128) PREF_BT(w1, 128, k0 + 32);
            #pragma unroll
            for (int kk = 0; kk < 32; kk++) {
                float a0 = res1[ty][k0+kk], a1 = res1[ty+8][k0+kk];
                float4 b4 = *(const float4*)&Bs[kk][tx*4];
                acc[0][0] = fmaf(a0, b4.x, acc[0][0]); acc[0][1] = fmaf(a0, b4.y, acc[0][1]);
                acc[0][2] = fmaf(a0, b4.z, acc[0][2]); acc[0][3] = fmaf(a0, b4.w, acc[0][3]);
                acc[1][0] = fmaf(a1, b4.x, acc[1][0]); acc[1][1] = fmaf(a1, b4.y, acc[1][1]);
                acc[1][2] = fmaf(a1, b4.z, acc[1][2]); acc[1][3] = fmaf(a1, b4.w, acc[1][3]);
            }
            __syncthreads();
        }
        float4 fb = *(const float4*)&ffn_b1[cb*128 + tx*4];
        #pragma unroll
        for (int i = 0; i < 2; i++) {
            float v[4];
            v[0] = acc[i][0] + fb.x; v[1] = acc[i][1] + fb.y;
            v[2] = acc[i][2] + fb.z; v[3] = acc[i][3] + fb.w;
            #pragma unroll
            for (int j = 0; j < 4; j++)
                v[j] = 0.5f*v[j]*(1.f + erff(v[j]*0.70710678118654752f));
            *(float4*)&actB[ty + 8*i][cb*128 + tx*4] = make_float4(v[0], v[1], v[2], v[3]);
        }
        __syncthreads();
    }

    // ---- stage C: FFN2 K=256 + LN2 ----
    {
        float acc[2][4] = {};
        PREF_BT(ffn_w2, 256, 0);
        for (int k0 = 0; k0 < 256; k0 += 32) {
            STORE_BT();
            __syncthreads();
            if (k0 + 32 < 256) PREF_BT(ffn_w2, 256, k0 + 32);
            #pragma unroll
            for (int kk = 0; kk < 32; kk++) {
                float a0 = actB[ty][k0+kk], a1 = actB[ty+8][k0+kk];
                float4 b4 = *(const float4*)&Bs[kk][tx*4];
                acc[0][0] = fmaf(a0, b4.x, acc[0][0]); acc[0][1] = fmaf(a0, b4.y, acc[0][1]);
                acc[0][2] = fmaf(a0, b4.z, acc[0][2]); acc[0][3] = fmaf(a0, b4.w, acc[0][3]);
                acc[1][0] = fmaf(a1, b4.x, acc[1][0]); acc[1][1] = fmaf(a1, b4.y, acc[1][1]);
                acc[1][2] = fmaf(a1, b4.z, acc[1][2]); acc[1][3] = fmaf(a1, b4.w, acc[1][3]);
            }
            __syncthreads();
        }
        float4 fb = *(const float4*)&ffn_b2[tx*4];
        float4 g4 = *(const float4*)&ln2_g[tx*4];
        float4 w4 = *(const float4*)&ln2_b[tx*4];
        #pragma unroll
        for (int i = 0; i < 2; i++) {
            int lr = ty + 8*i;
            float4 r4 = *(const float4*)&res1[lr][tx*4];
            float v[4];
            v[0] = acc[i][0] + fb.x + r4.x; v[1] = acc[i][1] + fb.y + r4.y;
            v[2] = acc[i][2] + fb.z + r4.z; v[3] = acc[i][3] + fb.w + r4.w;
            float m = warp_red_sum(v[0]+v[1]+v[2]+v[3]) * (1.f/128.f);
            float d2 = 0.f;
            #pragma unroll
            for (int j = 0; j < 4; j++) { float d = v[j]-m; d2 += d*d; }
            float var = warp_red_sum(d2) * (1.f/128.f);
            float inv = rsqrtf(var + 1e-5f);
            float4 o;
            o.x = (v[0]-m)*inv*g4.x + w4.x; o.y = (v[1]-m)*inv*g4.y + w4.y;
            o.z = (v[2]-m)*inv*g4.z + w4.z; o.w = (v[3]-m)*inv*g4.w + w4.w;
            *(float4*)&g_node3[(long)(rowbase+lr)*384 + tx*4] = o;
            *(float4*)&actB[lr][tx*4] = o;
        }
    }
    __syncthreads();
    for (int idx = tid; idx < 16*32; idx += 256) {
        int r = idx >> 5, c4 = idx & 31;
        *(float4*)&actB[r][128 + c4*4] =
            *(const float4*)&g_node3[(long)(rowbase+r)*384 + 128 + c4*4];
    }

    // ---- stage D: gh K=256 + s1/s2 ----
    {
        float acc[2][4] = {};
        PREF_BT(gat_w, 256, 0);
        for (int k0 = 0; k0 < 256; k0 += 32) {
            STORE_BT();
            __syncthreads();
            if (k0 + 32 < 256) PREF_BT(gat_w, 256, k0 + 32);
            #pragma unroll
            for (int kk = 0; kk < 32; kk++) {
                float a0 = actB[ty][k0+kk], a1 = actB[ty+8][k0+kk];
                float4 b4 = *(const float4*)&Bs[kk][tx*4];
                acc[0][0] = fmaf(a0, b4.x, acc[0][0]); acc[0][1] = fmaf(a0, b4.y, acc[0][1]);
                acc[0][2] = fmaf(a0, b4.z, acc[0][2]); acc[0][3] = fmaf(a0, b4.w, acc[0][3]);
                acc[1][0] = fmaf(a1, b4.x, acc[1][0]); acc[1][1] = fmaf(a1, b4.y, acc[1][1]);
                acc[1][2] = fmaf(a1, b4.z, acc[1][2]); acc[1][3] = fmaf(a1, b4.w, acc[1][3]);
            }
            __syncthreads();
        }
        float4 a1v = *(const float4*)&gat_a[tx*4];
        float4 a2v = *(const float4*)&gat_a[128 + tx*4];
        #pragma unroll
        for (int i = 0; i < 2; i++) {
            int r = rowbase + ty + 8*i;
            float4 o = make_float4(acc[i][0], acc[i][1], acc[i][2], acc[i][3]);
            *(float4*)&g_gh[(long)r*128 + tx*4] = o;
            float p1 = o.x*a1v.x + o.y*a1v.y + o.z*a1v.z + o.w*a1v.w;
            float p2 = o.x*a2v.x + o.y*a2v.y + o.z*a2v.z + o.w*a2v.w;
            p1 = warp_red_sum(p1);
            p2 = warp_red_sum(p2);
            if (tx == 0) { g_s1[r] = p1; g_s2[r] = p2; }
        }
    }
}

// ---------------- tail2: alpha + alpha@gh (R11 structure + prefetch) ----------------
__global__ __launch_bounds__(256) void tail2_kernel(const int* __restrict__ adj,
                                                    float* __restrict__ out_alpha)
{
    const int rowbase = blockIdx.x * 16;
    const int b = rowbase >> 9;
    __shared__ float alpha_sm[16][512];
    __shared__ float Bs2[32][128];
    const int tid = threadIdx.x;
    const int tx = tid & 31, ty = tid >> 5;

    #pragma unroll
    for (int rr = 0; rr < 2; rr++) {
        int lr = ty*2 + rr;
        int i = (rowbase + lr) & 511;
        float s1v = g_s1[rowbase + lr];
        float e[16];
        float mloc = -FLT_MAX;
        #pragma unroll
        for (int u = 0; u < 16; u++) {
            int j = tx + 32*u;
            float v = s1v + g_s2[b*N_ + j];
            v = (v >= 0.f) ? v : 0.2f*v;
            if (adj[i*N_ + j] == 0) v = -FLT_MAX;
            e[u] = v;
            mloc = fmaxf(mloc, v);
        }
        float m = warp_red_max(mloc);
        float sloc = 0.f;
        #pragma unroll
        for (int u = 0; u < 16; u++) {
            e[u] = (e[u] == -FLT_MAX) ? 0.f : __expf(e[u] - m);
            sloc += e[u];
        }
        float inv = 1.f / warp_red_sum(sloc);
        #pragma unroll
        for (int u = 0; u < 16; u++) {
            float a = e[u]*inv;
            alpha_sm[lr][tx + 32*u] = a;
            out_alpha[(long)(rowbase + lr)*N_ + tx + 32*u] = a;
        }
    }
    __syncthreads();

    const float* ghb = g_gh + (long)b*N_*H_;
    float4 pre[4];
    float acc[2][4] = {};
    #pragma unroll
    for (int it = 0; it < 4; it++) {
        int q = tid + it*256; int c4 = q & 31, kk = q >> 5;
        pre[it] = *(const float4*)&ghb[(long)kk*128 + c4*4];
    }
    for (int k0 = 0; k0 < 512; k0 += 32) {
        #pragma unroll
        for (int it = 0; it < 4; it++) {
            int q = tid + it*256; int c4 = q & 31, kk = q >> 5;
            *(float4*)&Bs2[kk][c4*4] = pre[it];
        }
        __syncthreads();
        if (k0 + 32 < 512) {
            #pragma unroll
            for (int it = 0; it < 4; it++) {
                int q = tid + it*256; int c4 = q & 31, kk = q >> 5;
                pre[it] = *(const float4*)&ghb[(long)(k0 + 32 + kk)*128 + c4*4];
            }
        }
        #pragma unroll
        for (int kk = 0; kk < 32; kk++) {
            float a0 = alpha_sm[ty][k0+kk], a1 = alpha_sm[ty+8][k0+kk];
            float4 b4 = *(const float4*)&Bs2[kk][tx*4];
            acc[0][0] = fmaf(a0, b4.x, acc[0][0]); acc[0][1] = fmaf(a0, b4.y, acc[0][1]);
            acc[0][2] = fmaf(a0, b4.z, acc[0][2]); acc[0][3] = fmaf(a0, b4.w, acc[0][3]);
            acc[1][0] = fmaf(a1, b4.x, acc[1][0]); acc[1][1] = fmaf(a1, b4.y, acc[1][1]);
            acc[1][2] = fmaf(a1, b4.z, acc[1][2]); acc[1][3] = fmaf(a1, b4.w, acc[1][3]);
        }
        __syncthreads();
    }
    #pragma unroll
    for (int i = 0; i < 2; i++) {
        int r = rowbase + ty + 8*i;
        *(float4*)&g_node3[(long)r*384 + 256 + tx*4] =
            make_float4(acc[i][0], acc[i][1], acc[i][2], acc[i][3]);
    }
}

// ---------------- fuse (relu) + heads (R11 structure + prefetch) ----------------
__global__ __launch_bounds__(256) void fuse_kernel(
    const float* __restrict__ fuse_w, const float* __restrict__ fuse_b,
    const float* __restrict__ hwreg, const float* __restrict__ hbreg,
    const float* __restrict__ hwrisk, const float* __restrict__ hbrisk,
    const float* __restrict__ hwwarn, const float* __restrict__ hbwarn,
    float* __restrict__ hout)
{
    const int rowbase = blockIdx.x * 16;
    __shared__ float As[32][17];
    __shared__ float Bs[32][132];
    const int tid = threadIdx.x;
    const int tx = tid & 31, ty = tid >> 5;
    float4 pre[4];
    float preA[2];
    float acc[2][4] = {};

    PREF_BT(fuse_w, 384, 0);
    #pragma unroll
    for (int it = 0; it < 2; it++) {
        int idx = tid + it*256; int r = idx >> 5, kk = idx & 31;
        preA[it] = g_node3[(long)(rowbase + r)*384 + kk];
    }
    for (int k0 = 0; k0 < 384; k0 += 32) {
        STORE_BT();
        #pragma unroll
        for (int it = 0; it < 2; it++) {
            int idx = tid + it*256; int r = idx >> 5, kk = idx & 31;
            As[kk][r] = preA[it];
        }
        __syncthreads();
        if (k0 + 32 < 384) {
            PREF_BT(fuse_w, 384, k0 + 32);
            #pragma unroll
            for (int it = 0; it < 2; it++) {
                int idx = tid + it*256; int r = idx >> 5, kk = idx & 31;
                preA[it] = g_node3[(long)(rowbase + r)*384 + k0 + 32 + kk];
            }
        }
        #pragma unroll
        for (int kk = 0; kk < 32; kk++) {
            float a0 = As[kk][ty], a1 = As[kk][ty + 8];
            float4 b4 = *(const float4*)&Bs[kk][tx*4];
            acc[0][0] = fmaf(a0, b4.x, acc[0][0]); acc[0][1] = fmaf(a0, b4.y, acc[0][1]);
            acc[0][2] = fmaf(a0, b4.z, acc[0][2]); acc[0][3] = fmaf(a0, b4.w, acc[0][3]);
            acc[1][0] = fmaf(a1, b4.x, acc[1][0]); acc[1][1] = fmaf(a1, b4.y, acc[1][1]);
            acc[1][2] = fmaf(a1, b4.z, acc[1][2]); acc[1][3] = fmaf(a1, b4.w, acc[1][3]);
        }
        __syncthreads();
    }
    float4 b4 = *(const float4*)&fuse_b[tx*4];
    #pragma unroll
    for (int i = 0; i < 2; i++) {
        float4 o;
        o.x = fmaxf(acc[i][0] + b4.x, 0.f); o.y = fmaxf(acc[i][1] + b4.y, 0.f);
        o.z = fmaxf(acc[i][2] + b4.z, 0.f); o.w = fmaxf(acc[i][3] + b4.w, 0.f);
        *(float4*)&Bs[ty + 8*i][tx*4] = o;
    }
    __syncthreads();
    for (int p = tid; p < 480; p += 256) {
        int r = p / 30, o = p - 30*r;
        const float* w; float bb; long off;
        if (o < 6)       { w = hwreg  + o*H_;        bb = hbreg[o];        off = OFF_REG  + (long)(rowbase+r)*6  + o; }
        else if (o < 24) { int k = o-6;  w = hwrisk + k*H_; bb = hbrisk[k]; off = OFF_RISK + (long)(rowbase+r)*18 + k; }
        else             { int k = o-24; w = hwwarn + k*H_; bb = hbwarn[k]; off = OFF_WARN + (long)(rowbase+r)*6  + k; }
        float sacc = bb;
        #pragma unroll 8
        for (int c = 0; c < H_; c++)
            sacc = fmaf(Bs[r][c], w[c], sacc);
        hout[off] = sacc;
    }
}

// ---------------- launch ----------------
extern "C" void kernel_launch(void* const* d_in, const int* in_sizes, int n_in,
                              void* d_out, int out_size)
{
    const float* x        = (const float*)d_in[0];
    const float* x_static = (const float*)d_in[1];
    const int*   adj      = (const int*)  d_in[2];
    const float* proj_w   = (const float*)d_in[3];
    const float* proj_b   = (const float*)d_in[4];
    const float* in_w     = (const float*)d_in[5];
    const float* in_b     = (const float*)d_in[6];
    const float* out_w    = (const float*)d_in[7];
    const float* out_b    = (const float*)d_in[8];
    const float* ln1_g    = (const float*)d_in[9];
    const float* ln1_b    = (const float*)d_in[10];
    const float* ffn_w1   = (const float*)d_in[11];
    const float* ffn_b1   = (const float*)d_in[12];
    const float* ffn_w2   = (const float*)d_in[13];
    const float* ffn_b2   = (const float*)d_in[14];
    const float* ln2_g    = (const float*)d_in[15];
    const float* ln2_b    = (const float*)d_in[16];
    const float* stat_w   = (const float*)d_in[17];
    const float* stat_b   = (const float*)d_in[18];
    const float* gat_w    = (const float*)d_in[19];
    const float* gat_a    = (const float*)d_in[20];
    const float* fuse_w   = (const float*)d_in[21];
    const float* fuse_b   = (const float*)d_in[22];
    const float* reg_w    = (const float*)d_in[23];
    const float* reg_b    = (const float*)d_in[24];
    const float* risk_w   = (const float*)d_in[25];
    const float* risk_b   = (const float*)d_in[26];
    const float* warn_w   = (const float*)d_in[27];
    const float* warn_b   = (const float*)d_in[28];
    float* out = (float*)d_out;

    const int ATTN4_SMEM = ATTN4_FLOATS * 4;  // 57856 bytes
    cudaFuncSetAttribute(attn4_kernel, cudaFuncAttributeMaxDynamicSharedMemorySize, ATTN4_SMEM);

    prep_kernel<<<1, 384>>>(in_w, in_b, proj_w, proj_b);
    attn4_kernel<<<BN_, 256, ATTN4_SMEM>>>(x, proj_w, proj_b, x_static, stat_w, stat_b,
                                           out + OFF_TATTN);
    tail1_kernel<<<BN_/16, 256>>>(out_w, out_b, ln1_g, ln1_b,
                                  ffn_w1, ffn_b1, ffn_w2, ffn_b2, ln2_g, ln2_b,
                                  gat_w, gat_a);
    tail2_kernel<<<BN_/16, 256>>>(adj, out + OFF_ALPHA);
    fuse_kernel<<<BN_/16, 256>>>(fuse_w, fuse_b,
                                 reg_w, reg_b, risk_w, risk_b, warn_w, warn_b, out);

    (void)in_sizes; (void)n_in; (void)out_size;
}